// round 1
// baseline (speedup 1.0000x reference)
#include <cuda_runtime.h>
#include <cstdint>

// Problem constants (SGC_63677185130849): N=100000 nodes, E=1600000 edges,
// D=50 features, C=47 classes, K=2 hops.
#define MAX_N 100000
#define MAX_E 1600000
#define D_FEAT 50
#define N_CLS 47
#define CHUNKS 25          // 50 floats = 25 float2 per row

// Scratch (device globals — no allocations allowed)
__device__ float g_h0[MAX_N * D_FEAT];   // hop-1 output
__device__ float g_h1[MAX_N * D_FEAT];   // hop-2 output
__device__ float g_dinv[MAX_N];
__device__ float g_we[MAX_E];
__device__ int   g_cnt[MAX_N];

// ---------------- degree / normalization ----------------

__global__ void k_zero_cnt(int N) {
    int i = blockIdx.x * blockDim.x + threadIdx.x;
    if (i < N) g_cnt[i] = 0;
}

__global__ void k_count(const int* __restrict__ dst, int E) {
    int i = blockIdx.x * blockDim.x + threadIdx.x;
    if (i < E) atomicAdd(&g_cnt[dst[i]], 1);
}

__global__ void k_dinv(int N) {
    int i = blockIdx.x * blockDim.x + threadIdx.x;
    if (i < N) g_dinv[i] = rsqrtf(1.0f + (float)g_cnt[i]);
}

__global__ void k_we(const int* __restrict__ src, const int* __restrict__ dst, int E) {
    int i = blockIdx.x * blockDim.x + threadIdx.x;
    if (i < E) g_we[i] = g_dinv[src[i]] * g_dinv[dst[i]];
}

// ---------------- propagation ----------------

// h_out[n] = dinv[n]^2 * h_in[n]  (self-loop term; also serves as the init
// of the accumulator before the edge-scatter pass)
__global__ void k_self(const float* __restrict__ hin, float* __restrict__ hout, int N) {
    int idx = blockIdx.x * blockDim.x + threadIdx.x;
    int total = N * D_FEAT;
    if (idx < total) {
        int n = idx / D_FEAT;
        float w = g_dinv[n];
        hout[idx] = (w * w) * hin[idx];
    }
}

__device__ __forceinline__ void red_add_v2(float* addr, float x, float y) {
    asm volatile("red.global.add.v2.f32 [%0], {%1, %2};"
                 :: "l"(addr), "f"(x), "f"(y) : "memory");
}

// One thread per (edge, float2 chunk). 25 threads per edge.
__global__ void k_edge(const float* __restrict__ hin, float* __restrict__ hout,
                       const int* __restrict__ src, const int* __restrict__ dst,
                       int E) {
    int t = blockIdx.x * blockDim.x + threadIdx.x;
    int total = E * CHUNKS;
    if (t >= total) return;
    int e = t / CHUNKS;
    int c = t - e * CHUNKS;
    int s = src[e];
    int d = dst[e];
    float w = g_we[e];
    const float2 v = *reinterpret_cast<const float2*>(hin + (size_t)s * D_FEAT + 2 * c);
    red_add_v2(hout + (size_t)d * D_FEAT + 2 * c, w * v.x, w * v.y);
}

// ---------------- final projection out = h @ W^T + b ----------------

#define GEMM_NODES 128

__global__ void k_gemm(const float* __restrict__ h, const float* __restrict__ W,
                       const float* __restrict__ b, float* __restrict__ out, int N) {
    __shared__ float Ws[N_CLS * D_FEAT];      // 9400 B
    __shared__ float bs[N_CLS];
    __shared__ float ht[GEMM_NODES * (D_FEAT + 1)];  // padded to 51 -> conflict-free

    int tid = threadIdx.x;
    // load W + b
    for (int i = tid; i < N_CLS * D_FEAT; i += GEMM_NODES) Ws[i] = W[i];
    if (tid < N_CLS) bs[tid] = b[tid];

    int n0 = blockIdx.x * GEMM_NODES;
    int nodes = min(GEMM_NODES, N - n0);

    // coalesced load of the h tile
    for (int i = tid; i < nodes * D_FEAT; i += GEMM_NODES) {
        int nl = i / D_FEAT;
        int f = i - nl * D_FEAT;
        ht[nl * (D_FEAT + 1) + f] = h[(size_t)(n0 + nl) * D_FEAT + f];
    }
    __syncthreads();

    if (tid < nodes) {
        const float* row = &ht[tid * (D_FEAT + 1)];
        float* orow = out + (size_t)(n0 + tid) * N_CLS;
        #pragma unroll 1
        for (int cc = 0; cc < N_CLS; cc++) {
            float acc = bs[cc];
            const float* wr = &Ws[cc * D_FEAT];
            #pragma unroll
            for (int f = 0; f < D_FEAT; f++) acc += row[f] * wr[f];
            orow[cc] = acc;
        }
    }
}

// ---------------- launch ----------------

extern "C" void kernel_launch(void* const* d_in, const int* in_sizes, int n_in,
                              void* d_out, int out_size) {
    const float* feat = (const float*)d_in[0];
    const float* W    = (const float*)d_in[1];
    const float* b    = (const float*)d_in[2];
    const int* esrc   = (const int*)d_in[3];
    const int* edst   = (const int*)d_in[4];
    // d_in[5] = K (device scalar). Hop count is statically unrolled to 2
    // (K_HOPS is fixed for this problem; graph capture requires a static
    // launch structure).

    int C = in_sizes[2];                // 47
    int D = in_sizes[1] / C;            // 50
    int N = in_sizes[0] / D;            // 100000
    int E = in_sizes[3];                // 1600000

    float* h0; cudaGetSymbolAddress((void**)&h0, g_h0);
    float* h1; cudaGetSymbolAddress((void**)&h1, g_h1);

    const int T = 256;
    // degree + normalization
    k_zero_cnt<<<(N + T - 1) / T, T>>>(N);
    k_count<<<(E + T - 1) / T, T>>>(edst, E);
    k_dinv<<<(N + T - 1) / T, T>>>(N);
    k_we<<<(E + T - 1) / T, T>>>(esrc, edst, E);

    int edge_work = E * CHUNKS;
    int edge_blocks = (edge_work + T - 1) / T;

    // hop 1: feat -> h0
    k_self<<<(N * D_FEAT + T - 1) / T, T>>>(feat, h0, N);
    k_edge<<<edge_blocks, T>>>(feat, h0, esrc, edst, E);

    // hop 2: h0 -> h1
    k_self<<<(N * D_FEAT + T - 1) / T, T>>>(h0, h1, N);
    k_edge<<<edge_blocks, T>>>(h0, h1, esrc, edst, E);

    // projection
    k_gemm<<<(N + GEMM_NODES - 1) / GEMM_NODES, GEMM_NODES>>>(h1, W, b, (float*)d_out, N);
}

// round 3
// speedup vs baseline: 1.5068x; 1.5068x over previous
#include <cuda_runtime.h>
#include <cstdint>

// SGC_63677185130849: N=100000 nodes, E=1600000 edges, D=50, C=47, K=2 hops.
#define MAX_N 100000
#define MAX_E 1600000
#define D_FEAT 50
#define N_CLS 47
#define SCAN_B 1024                 // elements per scan block
#define MAX_SB 128                  // max scan blocks (N <= 131072)

// Scratch (device globals — allocations are forbidden)
__device__ float g_h0[MAX_N * D_FEAT];
__device__ float g_h1[MAX_N * D_FEAT];
__device__ float g_dinv[MAX_N];
__device__ int   g_cnt[MAX_N];
__device__ int   g_scan[MAX_N];     // within-block inclusive scan of cnt
__device__ int   g_bsum[MAX_SB];    // block sums (scanned in place)
__device__ int   g_off[MAX_N + 1];  // CSR row offsets (by dst)
__device__ int   g_cur[MAX_N];      // scatter cursors
__device__ int   g_csrc[MAX_E];     // CSR: source node per slot
__device__ float g_cw[MAX_E];       // CSR: edge weight per slot

// ---------------- degree ----------------

__global__ void k_zero(int N) {
    int i = blockIdx.x * blockDim.x + threadIdx.x;
    if (i < N) g_cnt[i] = 0;
}

__global__ void k_count(const int* __restrict__ dst, int E) {
    int i = blockIdx.x * blockDim.x + threadIdx.x;
    if (i < E) atomicAdd(&g_cnt[dst[i]], 1);
}

__global__ void k_dinv(int N) {
    int i = blockIdx.x * blockDim.x + threadIdx.x;
    if (i < N) g_dinv[i] = rsqrtf(1.0f + (float)g_cnt[i]);
}

// ---------------- prefix scan (3 kernels) ----------------

__global__ void k_scan1(int N) {
    __shared__ int s[SCAN_B];
    int t = threadIdx.x;
    int i = blockIdx.x * SCAN_B + t;
    int v = (i < N) ? g_cnt[i] : 0;
    s[t] = v;
    __syncthreads();
    for (int o = 1; o < SCAN_B; o <<= 1) {
        int x = (t >= o) ? s[t - o] : 0;
        __syncthreads();
        s[t] += x;
        __syncthreads();
    }
    if (i < N) g_scan[i] = s[t];
    if (t == SCAN_B - 1) g_bsum[blockIdx.x] = s[t];
}

__global__ void k_scan2(int NB) {
    __shared__ int s[MAX_SB];
    int t = threadIdx.x;
    int v = (t < NB) ? g_bsum[t] : 0;
    s[t] = v;
    __syncthreads();
    for (int o = 1; o < MAX_SB; o <<= 1) {
        int x = (t >= o) ? s[t - o] : 0;
        __syncthreads();
        s[t] += x;
        __syncthreads();
    }
    if (t < NB) g_bsum[t] = s[t];
}

__global__ void k_scan3(int N, int E) {
    int i = blockIdx.x * blockDim.x + threadIdx.x;
    if (i > N) return;
    int excl;
    if (i == 0) excl = 0;
    else if (i == N) excl = E;
    else {
        int j = i - 1;
        int b = j / SCAN_B;
        excl = g_scan[j] + (b > 0 ? g_bsum[b - 1] : 0);
    }
    g_off[i] = excl;
    if (i < N) g_cur[i] = excl;
}

// ---------------- CSR scatter ----------------

__global__ void k_scatter(const int* __restrict__ src, const int* __restrict__ dst, int E) {
    int i = blockIdx.x * blockDim.x + threadIdx.x;
    if (i < E) {
        int s = src[i];
        int d = dst[i];
        int p = atomicAdd(&g_cur[d], 1);
        g_csrc[p] = s;
        g_cw[p] = g_dinv[s] * g_dinv[d];
    }
}

// ---------------- propagation: warp-per-node gather ----------------

__global__ void __launch_bounds__(256) k_gather(const float* __restrict__ hin,
                                                float* __restrict__ hout, int N) {
    int warp = (blockIdx.x * blockDim.x + threadIdx.x) >> 5;
    int lane = threadIdx.x & 31;
    if (warp >= N) return;
    int n = warp;

    int base = g_off[n];
    int end  = g_off[n + 1];

    float dv = g_dinv[n];
    float selfw = dv * dv;

    float2 acc = make_float2(0.f, 0.f);
    if (lane < 25) {
        float2 v = *reinterpret_cast<const float2*>(hin + (size_t)n * D_FEAT + 2 * lane);
        acc.x = selfw * v.x;
        acc.y = selfw * v.y;
    }

    for (int i = base; i < end; i += 32) {
        int k = i + lane;
        int s = 0;
        float w = 0.f;
        if (k < end) { s = g_csrc[k]; w = g_cw[k]; }
        int m = min(32, end - i);
        #pragma unroll 4
        for (int j = 0; j < m; j++) {
            int   ss = __shfl_sync(0xffffffffu, s, j);
            float ww = __shfl_sync(0xffffffffu, w, j);
            if (lane < 25) {
                float2 v = *reinterpret_cast<const float2*>(hin + (size_t)ss * D_FEAT + 2 * lane);
                acc.x += ww * v.x;
                acc.y += ww * v.y;
            }
        }
    }

    if (lane < 25) {
        *reinterpret_cast<float2*>(hout + (size_t)n * D_FEAT + 2 * lane) = acc;
    }
}

// ---------------- projection out = h @ W^T + b ----------------

#define GEMM_NODES 128

__global__ void k_gemm(const float* __restrict__ h, const float* __restrict__ W,
                       const float* __restrict__ b, float* __restrict__ out, int N) {
    __shared__ float Ws[N_CLS * D_FEAT];
    __shared__ float bs[N_CLS];
    __shared__ float ht[GEMM_NODES * (D_FEAT + 1)];

    int tid = threadIdx.x;
    for (int i = tid; i < N_CLS * D_FEAT; i += GEMM_NODES) Ws[i] = W[i];
    if (tid < N_CLS) bs[tid] = b[tid];

    int n0 = blockIdx.x * GEMM_NODES;
    int nodes = min(GEMM_NODES, N - n0);

    for (int i = tid; i < nodes * D_FEAT; i += GEMM_NODES) {
        int nl = i / D_FEAT;
        int f = i - nl * D_FEAT;
        ht[nl * (D_FEAT + 1) + f] = h[(size_t)(n0 + nl) * D_FEAT + f];
    }
    __syncthreads();

    if (tid < nodes) {
        const float* row = &ht[tid * (D_FEAT + 1)];
        float* orow = out + (size_t)(n0 + tid) * N_CLS;
        #pragma unroll 1
        for (int cc = 0; cc < N_CLS; cc++) {
            float acc = bs[cc];
            const float* wr = &Ws[cc * D_FEAT];
            #pragma unroll
            for (int f = 0; f < D_FEAT; f++) acc += row[f] * wr[f];
            orow[cc] = acc;
        }
    }
}

// ---------------- launch ----------------

extern "C" void kernel_launch(void* const* d_in, const int* in_sizes, int n_in,
                              void* d_out, int out_size) {
    const float* feat = (const float*)d_in[0];
    const float* W    = (const float*)d_in[1];
    const float* b    = (const float*)d_in[2];
    const int* esrc   = (const int*)d_in[3];
    const int* edst   = (const int*)d_in[4];
    // d_in[5] = K (device scalar); hops statically unrolled to 2 (fixed for
    // this problem; graph capture needs static structure).

    int C = in_sizes[2];
    int D = in_sizes[1] / C;
    int N = in_sizes[0] / D;
    int E = in_sizes[3];

    float* h0; cudaGetSymbolAddress((void**)&h0, g_h0);
    float* h1; cudaGetSymbolAddress((void**)&h1, g_h1);

    const int T = 256;
    int NB = (N + SCAN_B - 1) / SCAN_B;

    // degree + dinv
    k_zero<<<(N + T - 1) / T, T>>>(N);
    k_count<<<(E + T - 1) / T, T>>>(edst, E);
    k_dinv<<<(N + T - 1) / T, T>>>(N);

    // CSR offsets (exclusive scan of counts)
    k_scan1<<<NB, SCAN_B>>>(N);
    k_scan2<<<1, MAX_SB>>>(NB);
    k_scan3<<<(N + 1 + T - 1) / T, T>>>(N, E);

    // CSR scatter (also materializes edge weights)
    k_scatter<<<(E + T - 1) / T, T>>>(esrc, edst, E);

    // 2 hops: warp-per-node gather
    int gblocks = (N * 32 + T - 1) / T;
    k_gather<<<gblocks, T>>>(feat, h0, N);
    k_gather<<<gblocks, T>>>(h0, h1, N);

    // projection
    k_gemm<<<(N + GEMM_NODES - 1) / GEMM_NODES, GEMM_NODES>>>(h1, W, b, (float*)d_out, N);
}

// round 4
// speedup vs baseline: 1.7318x; 1.1493x over previous
#include <cuda_runtime.h>
#include <cuda_fp16.h>
#include <cstdint>

// SGC_63677185130849: N=100000 nodes, E=1600000 edges, D=50, C=47, K=2 hops.
#define MAX_N 100000
#define MAX_E 1600000
#define D_FEAT 50
#define N_CLS 47
#define HCHUNKS 25                  // 50 halves = 25 half2 per row
#define SCAN_B 1024
#define MAX_SB 128

// Scratch (device globals — allocations forbidden)
__device__ __half g_ha[MAX_N * D_FEAT];   // fp16 feature ping
__device__ __half g_hb[MAX_N * D_FEAT];   // fp16 feature pong
__device__ float  g_dinv[MAX_N];
__device__ int    g_cnt[MAX_N];
__device__ int    g_scan[MAX_N];
__device__ int    g_bsum[MAX_SB];
__device__ int    g_off[MAX_N + 1];
__device__ int    g_cur[MAX_N];
__device__ int2   g_cedge[MAX_E];         // packed CSR: {src, __float_as_int(w)}

// ---------------- degree ----------------

__global__ void k_count(const int* __restrict__ dst, int E) {
    int i = blockIdx.x * blockDim.x + threadIdx.x;
    if (i < E) atomicAdd(&g_cnt[dst[i]], 1);
}

// ---------------- scan (3 kernels); scan1 also computes dinv ----------------

__global__ void k_scan1(int N) {
    __shared__ int s[SCAN_B];
    int t = threadIdx.x;
    int i = blockIdx.x * SCAN_B + t;
    int v = (i < N) ? g_cnt[i] : 0;
    if (i < N) g_dinv[i] = rsqrtf(1.0f + (float)v);
    s[t] = v;
    __syncthreads();
    for (int o = 1; o < SCAN_B; o <<= 1) {
        int x = (t >= o) ? s[t - o] : 0;
        __syncthreads();
        s[t] += x;
        __syncthreads();
    }
    if (i < N) g_scan[i] = s[t];
    if (t == SCAN_B - 1) g_bsum[blockIdx.x] = s[t];
}

__global__ void k_scan2(int NB) {
    __shared__ int s[MAX_SB];
    int t = threadIdx.x;
    int v = (t < NB) ? g_bsum[t] : 0;
    s[t] = v;
    __syncthreads();
    for (int o = 1; o < MAX_SB; o <<= 1) {
        int x = (t >= o) ? s[t - o] : 0;
        __syncthreads();
        s[t] += x;
        __syncthreads();
    }
    if (t < NB) g_bsum[t] = s[t];
}

__global__ void k_scan3(int N, int E) {
    int i = blockIdx.x * blockDim.x + threadIdx.x;
    if (i > N) return;
    int excl;
    if (i == 0) excl = 0;
    else if (i == N) excl = E;
    else {
        int j = i - 1;
        int b = j / SCAN_B;
        excl = g_scan[j] + (b > 0 ? g_bsum[b - 1] : 0);
    }
    g_off[i] = excl;
    if (i < N) g_cur[i] = excl;
}

// ---------------- feat fp32 -> fp16 ----------------

__global__ void k_feat2h(const float* __restrict__ feat, int total2) {
    int i = blockIdx.x * blockDim.x + threadIdx.x;
    if (i < total2) {
        float2 v = *reinterpret_cast<const float2*>(feat + 2 * i);
        *reinterpret_cast<__half2*>(g_ha + 2 * i) = __float22half2_rn(v);
    }
}

// ---------------- CSR scatter (packed {src, w}) ----------------

__global__ void k_scatter(const int* __restrict__ src, const int* __restrict__ dst, int E) {
    int i = blockIdx.x * blockDim.x + threadIdx.x;
    if (i < E) {
        int s = src[i];
        int d = dst[i];
        int p = atomicAdd(&g_cur[d], 1);
        float w = g_dinv[s] * g_dinv[d];
        g_cedge[p] = make_int2(s, __float_as_int(w));
    }
}

// ---------------- propagation: warp-per-node gather (fp16 rows) ----------------

__global__ void __launch_bounds__(256) k_gather(const __half* __restrict__ hin,
                                                __half* __restrict__ hout, int N) {
    int warp = (blockIdx.x * blockDim.x + threadIdx.x) >> 5;
    int lane = threadIdx.x & 31;
    if (warp >= N) return;
    int n = warp;

    int base = g_off[n];
    int end  = g_off[n + 1];

    float dv = g_dinv[n];
    float selfw = dv * dv;

    float2 acc = make_float2(0.f, 0.f);
    if (lane < HCHUNKS) {
        __half2 v = *reinterpret_cast<const __half2*>(hin + (size_t)n * D_FEAT + 2 * lane);
        float2 f = __half22float2(v);
        acc.x = selfw * f.x;
        acc.y = selfw * f.y;
    }

    for (int i = base; i < end; i += 32) {
        int k = i + lane;
        int2 pe = make_int2(0, 0);
        if (k < end) pe = g_cedge[k];
        int m = min(32, end - i);
        #pragma unroll 4
        for (int j = 0; j < m; j++) {
            int   ss = __shfl_sync(0xffffffffu, pe.x, j);
            int   wi = __shfl_sync(0xffffffffu, pe.y, j);
            if (lane < HCHUNKS) {
                float ww = __int_as_float(wi);
                __half2 v = *reinterpret_cast<const __half2*>(hin + (size_t)ss * D_FEAT + 2 * lane);
                float2 f = __half22float2(v);
                acc.x += ww * f.x;
                acc.y += ww * f.y;
            }
        }
    }

    if (lane < HCHUNKS) {
        *reinterpret_cast<__half2*>(hout + (size_t)n * D_FEAT + 2 * lane) =
            __float22half2_rn(acc);
    }
}

// ---------------- projection out = h @ W^T + b (fp16 h input) ----------------

#define GEMM_NODES 128

__global__ void k_gemm(const __half* __restrict__ h, const float* __restrict__ W,
                       const float* __restrict__ b, float* __restrict__ out, int N) {
    __shared__ float Ws[N_CLS * D_FEAT];
    __shared__ float bs[N_CLS];
    __shared__ float ht[GEMM_NODES * (D_FEAT + 1)];

    int tid = threadIdx.x;
    for (int i = tid; i < N_CLS * D_FEAT; i += GEMM_NODES) Ws[i] = W[i];
    if (tid < N_CLS) bs[tid] = b[tid];

    int n0 = blockIdx.x * GEMM_NODES;
    int nodes = min(GEMM_NODES, N - n0);

    for (int i = tid; i < nodes * HCHUNKS; i += GEMM_NODES) {
        int nl = i / HCHUNKS;
        int c = i - nl * HCHUNKS;
        __half2 v = *reinterpret_cast<const __half2*>(h + (size_t)(n0 + nl) * D_FEAT + 2 * c);
        float2 f = __half22float2(v);
        ht[nl * (D_FEAT + 1) + 2 * c]     = f.x;
        ht[nl * (D_FEAT + 1) + 2 * c + 1] = f.y;
    }
    __syncthreads();

    if (tid < nodes) {
        const float* row = &ht[tid * (D_FEAT + 1)];
        float* orow = out + (size_t)(n0 + tid) * N_CLS;
        #pragma unroll 1
        for (int cc = 0; cc < N_CLS; cc++) {
            float acc = bs[cc];
            const float* wr = &Ws[cc * D_FEAT];
            #pragma unroll
            for (int f = 0; f < D_FEAT; f++) acc += row[f] * wr[f];
            orow[cc] = acc;
        }
    }
}

// ---------------- launch ----------------

extern "C" void kernel_launch(void* const* d_in, const int* in_sizes, int n_in,
                              void* d_out, int out_size) {
    const float* feat = (const float*)d_in[0];
    const float* W    = (const float*)d_in[1];
    const float* b    = (const float*)d_in[2];
    const int* esrc   = (const int*)d_in[3];
    const int* edst   = (const int*)d_in[4];
    // d_in[5] = K (device scalar); hops statically unrolled to 2.

    int C = in_sizes[2];
    int D = in_sizes[1] / C;
    int N = in_sizes[0] / D;
    int E = in_sizes[3];

    __half* ha; cudaGetSymbolAddress((void**)&ha, g_ha);
    __half* hb; cudaGetSymbolAddress((void**)&hb, g_hb);
    int* cnt;   cudaGetSymbolAddress((void**)&cnt, g_cnt);

    const int T = 256;
    int NB = (N + SCAN_B - 1) / SCAN_B;

    // degree + dinv
    cudaMemsetAsync(cnt, 0, (size_t)N * sizeof(int));
    k_count<<<(E + T - 1) / T, T>>>(edst, E);
    k_scan1<<<NB, SCAN_B>>>(N);
    k_scan2<<<1, MAX_SB>>>(NB);
    k_scan3<<<(N + 1 + T - 1) / T, T>>>(N, E);

    // fp16 conversion of feat (independent of CSR build)
    int total2 = N * D_FEAT / 2;
    k_feat2h<<<(total2 + T - 1) / T, T>>>(feat, total2);

    // CSR scatter (packed edge records)
    k_scatter<<<(E + T - 1) / T, T>>>(esrc, edst, E);

    // 2 hops
    int gblocks = (N * 32 + T - 1) / T;
    k_gather<<<gblocks, T>>>(ha, hb, N);
    k_gather<<<gblocks, T>>>(hb, ha, N);

    // projection
    k_gemm<<<(N + GEMM_NODES - 1) / GEMM_NODES, GEMM_NODES>>>(ha, W, b, (float*)d_out, N);
}

// round 6
// speedup vs baseline: 1.9683x; 1.1366x over previous
#include <cuda_runtime.h>
#include <cuda_fp16.h>
#include <cstdint>

// SGC_63677185130849: N=100000 nodes, E=1600000 edges, D=50, C=47, K=2 hops.
#define MAX_N 100000
#define MAX_E 1600000
#define D_FEAT 50
#define N_CLS 47
#define HCHUNKS 25                  // 50 halves = 25 half2 per row
#define ROW_BYTES 100               // fp16 row stride in bytes
#define SCAN_B 1024
#define MAX_SB 128

// Scratch (device globals — allocations forbidden)
__device__ __align__(16) __half g_ha[MAX_N * D_FEAT];
__device__ __align__(16) __half g_hb[MAX_N * D_FEAT];
__device__ float  g_dinv[MAX_N];
__device__ int    g_cnt[MAX_N];
__device__ int    g_scan[MAX_N];
__device__ int    g_bsum[MAX_SB];
__device__ int    g_off[MAX_N + 1];
__device__ int    g_cur[MAX_N];
__device__ int2   g_cedge[MAX_E];   // packed CSR: {src_byte_off, f32bits(dinv[src])}

// ---- packed fp32x2 FMA (Blackwell FFMA2; PTX-only, ptxas never auto-fuses) ----
__device__ __forceinline__ void fma_f32x2(float2& d, float2 a, float2 b) {
    asm("fma.rn.f32x2 %0, %1, %2, %0;"
        : "+l"(*reinterpret_cast<unsigned long long*>(&d))
        : "l"(*reinterpret_cast<unsigned long long*>(&a)),
          "l"(*reinterpret_cast<unsigned long long*>(&b)));
}

// ---------------- degree count + feat fp32->fp16 (fused) ----------------
// NOTE: grid must cover max(E, total2) — Round-5 bug was launching only E.

__global__ void k_count_conv(const int* __restrict__ dst, const float* __restrict__ feat,
                             int E, int total2) {
    int i = blockIdx.x * blockDim.x + threadIdx.x;
    if (i < E) atomicAdd(&g_cnt[dst[i]], 1);
    if (i < total2) {
        float2 v = reinterpret_cast<const float2*>(feat)[i];
        reinterpret_cast<__half2*>(g_ha)[i] = __float22half2_rn(v);
    }
}

// ---------------- scan (3 kernels); scan1 also computes dinv ----------------

__global__ void k_scan1(int N) {
    __shared__ int ws[32];
    int t = threadIdx.x;
    int i = blockIdx.x * SCAN_B + t;
    int v = (i < N) ? g_cnt[i] : 0;
    if (i < N) g_dinv[i] = rsqrtf(1.0f + (float)v);
    int x = v;
    #pragma unroll
    for (int o = 1; o < 32; o <<= 1) {
        int y = __shfl_up_sync(0xffffffffu, x, o);
        if ((t & 31) >= o) x += y;
    }
    if ((t & 31) == 31) ws[t >> 5] = x;
    __syncthreads();
    if (t < 32) {
        int y = ws[t];
        #pragma unroll
        for (int o = 1; o < 32; o <<= 1) {
            int z = __shfl_up_sync(0xffffffffu, y, o);
            if (t >= o) y += z;
        }
        ws[t] = y;
    }
    __syncthreads();
    int incl = x + ((t >= 32) ? ws[(t >> 5) - 1] : 0);
    if (i < N) g_scan[i] = incl;
    if (t == SCAN_B - 1) g_bsum[blockIdx.x] = incl;
}

__global__ void k_scan2(int NB) {
    __shared__ int s[MAX_SB];
    int t = threadIdx.x;
    int v = (t < NB) ? g_bsum[t] : 0;
    s[t] = v;
    __syncthreads();
    for (int o = 1; o < MAX_SB; o <<= 1) {
        int x = (t >= o) ? s[t - o] : 0;
        __syncthreads();
        s[t] += x;
        __syncthreads();
    }
    if (t < NB) g_bsum[t] = s[t];
}

__global__ void k_scan3(int N, int E) {
    int i = blockIdx.x * blockDim.x + threadIdx.x;
    if (i > N) return;
    int excl;
    if (i == 0) excl = 0;
    else if (i == N) excl = E;
    else {
        int j = i - 1;
        int b = j / SCAN_B;
        excl = g_scan[j] + (b > 0 ? g_bsum[b - 1] : 0);
    }
    g_off[i] = excl;
    if (i < N) g_cur[i] = excl;
}

// ---------------- CSR scatter: {src byte offset, dinv[src]} ----------------
// dinv[dst] is factored out and applied once per node in the gather.

__global__ void k_scatter(const int* __restrict__ src, const int* __restrict__ dst, int E) {
    int i = blockIdx.x * blockDim.x + threadIdx.x;
    if (i < E) {
        int s = src[i];
        int d = dst[i];
        int p = atomicAdd(&g_cur[d], 1);
        g_cedge[p] = make_int2(s * ROW_BYTES, __float_as_int(g_dinv[s]));
    }
}

// ---------------- propagation: warp-per-node gather ----------------
// hout[n] = dinv_n * ( dinv_n * hin[n] + sum_e dinv_src * hin[src] )

__global__ void __launch_bounds__(256) k_gather(const __half* __restrict__ hin,
                                                __half* __restrict__ hout, int N) {
    int warp = (blockIdx.x * blockDim.x + threadIdx.x) >> 5;
    int lane = threadIdx.x & 31;
    if (warp >= N) return;
    int n = warp;

    int base = g_off[n];
    int end  = g_off[n + 1];
    float dv = g_dinv[n];
    bool active = lane < HCHUNKS;

    const char* rowp = reinterpret_cast<const char*>(hin) + 4 * lane;

    float2 acc = make_float2(0.f, 0.f);
    if (active) {
        float2 f = __half22float2(
            *reinterpret_cast<const __half2*>(rowp + n * ROW_BYTES));
        acc.x = dv * f.x;
        acc.y = dv * f.y;
    }

    for (int i = base; i < end; i += 32) {
        int k = i + lane;
        int2 pe = make_int2(0, 0);
        if (k < end) pe = g_cedge[k];
        int m = min(32, end - i);
        #pragma unroll 4
        for (int j = 0; j < m; j++) {
            int   off = __shfl_sync(0xffffffffu, pe.x, j);
            float ww  = __int_as_float(__shfl_sync(0xffffffffu, pe.y, j));
            if (active) {
                float2 f = __half22float2(
                    *reinterpret_cast<const __half2*>(rowp + off));
                acc.x = fmaf(ww, f.x, acc.x);
                acc.y = fmaf(ww, f.y, acc.y);
            }
        }
    }

    if (active) {
        acc.x *= dv;
        acc.y *= dv;
        *reinterpret_cast<__half2*>(
            reinterpret_cast<char*>(hout) + n * ROW_BYTES + 4 * lane) =
            __float22half2_rn(acc);
    }
}

// ---------------- projection out = h @ W^T + b ----------------
// K-packed FFMA2 dots, row in registers, smem-staged coalesced stores.

#define GEMM_NODES 128

__global__ void __launch_bounds__(GEMM_NODES) k_gemm(const __half* __restrict__ h,
                                                     const float* __restrict__ W,
                                                     const float* __restrict__ b,
                                                     float* __restrict__ out, int N) {
    __shared__ float2 Ws2[N_CLS * HCHUNKS];                       // 9400 B
    __shared__ float bs[N_CLS];
    __shared__ __align__(16) char buf[HCHUNKS * GEMM_NODES * 8];  // 25600 B (union)
    float2* ht2 = reinterpret_cast<float2*>(buf);                 // [25][128]
    float*  ot  = reinterpret_cast<float*>(buf);                  // [128*47] (reuse)

    int tid = threadIdx.x;
    for (int i = tid; i < N_CLS * HCHUNKS; i += GEMM_NODES)
        Ws2[i] = reinterpret_cast<const float2*>(W)[i];
    if (tid < N_CLS) bs[tid] = b[tid];

    int n0 = blockIdx.x * GEMM_NODES;
    int nodes = min(GEMM_NODES, N - n0);

    // transposed fill: ht2[c][node]
    for (int i = tid; i < nodes * HCHUNKS; i += GEMM_NODES) {
        int nl = i / HCHUNKS;
        int c = i - nl * HCHUNKS;
        __half2 v = *reinterpret_cast<const __half2*>(
            reinterpret_cast<const char*>(h) + (size_t)(n0 + nl) * ROW_BYTES + 4 * c);
        ht2[c * GEMM_NODES + nl] = __half22float2(v);
    }
    __syncthreads();

    float2 row[HCHUNKS];
    if (tid < nodes) {
        #pragma unroll
        for (int c = 0; c < HCHUNKS; c++) row[c] = ht2[c * GEMM_NODES + tid];
    }
    __syncthreads();    // ht2 dead; buf becomes ot

    if (tid < nodes) {
        #pragma unroll 1
        for (int cc = 0; cc < N_CLS; cc++) {
            float2 a = make_float2(bs[cc], 0.f);
            const float2* wr = &Ws2[cc * HCHUNKS];
            #pragma unroll
            for (int c = 0; c < HCHUNKS; c++) fma_f32x2(a, row[c], wr[c]);
            ot[tid * N_CLS + cc] = a.x + a.y;
        }
    }
    __syncthreads();

    for (int i = tid; i < nodes * N_CLS; i += GEMM_NODES)
        out[(size_t)n0 * N_CLS + i] = ot[i];
}

// ---------------- launch ----------------

extern "C" void kernel_launch(void* const* d_in, const int* in_sizes, int n_in,
                              void* d_out, int out_size) {
    const float* feat = (const float*)d_in[0];
    const float* W    = (const float*)d_in[1];
    const float* b    = (const float*)d_in[2];
    const int* esrc   = (const int*)d_in[3];
    const int* edst   = (const int*)d_in[4];
    // d_in[5] = K (device scalar); hops statically unrolled to 2.

    int C = in_sizes[2];
    int D = in_sizes[1] / C;
    int N = in_sizes[0] / D;
    int E = in_sizes[3];

    __half* ha; cudaGetSymbolAddress((void**)&ha, g_ha);
    __half* hb; cudaGetSymbolAddress((void**)&hb, g_hb);
    int* cnt;   cudaGetSymbolAddress((void**)&cnt, g_cnt);

    const int T = 256;
    int NB = (N + SCAN_B - 1) / SCAN_B;
    int total2 = N * D_FEAT / 2;

    cudaMemsetAsync(cnt, 0, (size_t)N * sizeof(int));
    int fused_work = (E > total2) ? E : total2;          // FIX: cover both sides
    k_count_conv<<<(fused_work + T - 1) / T, T>>>(edst, feat, E, total2);
    k_scan1<<<NB, SCAN_B>>>(N);
    k_scan2<<<1, MAX_SB>>>(NB);
    k_scan3<<<(N + 1 + T - 1) / T, T>>>(N, E);
    k_scatter<<<(E + T - 1) / T, T>>>(esrc, edst, E);

    int gblocks = (N * 32 + T - 1) / T;
    k_gather<<<gblocks, T>>>(ha, hb, N);
    k_gather<<<gblocks, T>>>(hb, ha, N);

    k_gemm<<<(N + GEMM_NODES - 1) / GEMM_NODES, GEMM_NODES>>>(ha, W, b, (float*)d_out, N);
}

// round 7
// speedup vs baseline: 2.2257x; 1.1308x over previous
#include <cuda_runtime.h>
#include <cuda_fp16.h>
#include <cstdint>

// SGC_63677185130849: N=100000 nodes, E=1600000 edges, D=50, C=47, K=2 hops.
#define MAX_N 100000
#define MAX_E 1600000
#define D_FEAT 50
#define N_CLS 47
#define HCHUNKS 25                  // 50 real halves = 25 half2
#define ROW_HALVES 64               // padded to 128 bytes
#define ROW_BYTES 128
#define SCAN_B 1024
#define MAX_SB 128

// Scratch (device globals — allocations forbidden)
__device__ __align__(16) __half g_ha[MAX_N * ROW_HALVES];   // 12.8 MB
__device__ __align__(16) __half g_hb[MAX_N * ROW_HALVES];   // 12.8 MB
__device__ float  g_dinv[MAX_N];
__device__ int    g_cnt[MAX_N];
__device__ int    g_scan[MAX_N];
__device__ int    g_bsum[MAX_SB];
__device__ int    g_off[MAX_N + 1];
__device__ int    g_cur[MAX_N];
__device__ int2   g_cedge[MAX_E];   // packed CSR: {src_byte_off(128B rows), f32bits(dinv[src])}

// ---- packed fp32x2 FMA (Blackwell FFMA2; PTX-only) ----
__device__ __forceinline__ void fma_f32x2(float2& d, float2 a, float2 b) {
    asm("fma.rn.f32x2 %0, %1, %2, %0;"
        : "+l"(*reinterpret_cast<unsigned long long*>(&d))
        : "l"(*reinterpret_cast<unsigned long long*>(&a)),
          "l"(*reinterpret_cast<unsigned long long*>(&b)));
}

// ---------------- degree count + feat fp32 -> padded fp16 (fused) ----------------
// Grid must cover max(E, N*32).

__global__ void k_count_conv(const int* __restrict__ dst, const float* __restrict__ feat,
                             int E, int N) {
    int i = blockIdx.x * blockDim.x + threadIdx.x;
    if (i < E) atomicAdd(&g_cnt[dst[i]], 1);
    int total = N * 32;                       // half2 slots in padded matrix
    if (i < total) {
        int row = i >> 5;
        int c = i & 31;
        float2 v = make_float2(0.f, 0.f);
        if (c < HCHUNKS) v = reinterpret_cast<const float2*>(feat)[row * HCHUNKS + c];
        reinterpret_cast<__half2*>(g_ha)[i] = __float22half2_rn(v);
    }
}

// ---------------- scan (3 kernels); scan1 also computes dinv ----------------

__global__ void k_scan1(int N) {
    __shared__ int ws[32];
    int t = threadIdx.x;
    int i = blockIdx.x * SCAN_B + t;
    int v = (i < N) ? g_cnt[i] : 0;
    if (i < N) g_dinv[i] = rsqrtf(1.0f + (float)v);
    int x = v;
    #pragma unroll
    for (int o = 1; o < 32; o <<= 1) {
        int y = __shfl_up_sync(0xffffffffu, x, o);
        if ((t & 31) >= o) x += y;
    }
    if ((t & 31) == 31) ws[t >> 5] = x;
    __syncthreads();
    if (t < 32) {
        int y = ws[t];
        #pragma unroll
        for (int o = 1; o < 32; o <<= 1) {
            int z = __shfl_up_sync(0xffffffffu, y, o);
            if (t >= o) y += z;
        }
        ws[t] = y;
    }
    __syncthreads();
    int incl = x + ((t >= 32) ? ws[(t >> 5) - 1] : 0);
    if (i < N) g_scan[i] = incl;
    if (t == SCAN_B - 1) g_bsum[blockIdx.x] = incl;
}

__global__ void k_scan2(int NB) {
    __shared__ int s[MAX_SB];
    int t = threadIdx.x;
    int v = (t < NB) ? g_bsum[t] : 0;
    s[t] = v;
    __syncthreads();
    for (int o = 1; o < MAX_SB; o <<= 1) {
        int x = (t >= o) ? s[t - o] : 0;
        __syncthreads();
        s[t] += x;
        __syncthreads();
    }
    if (t < NB) g_bsum[t] = s[t];
}

__global__ void k_scan3(int N, int E) {
    int i = blockIdx.x * blockDim.x + threadIdx.x;
    if (i > N) return;
    int excl;
    if (i == 0) excl = 0;
    else if (i == N) excl = E;
    else {
        int j = i - 1;
        int b = j / SCAN_B;
        excl = g_scan[j] + (b > 0 ? g_bsum[b - 1] : 0);
    }
    g_off[i] = excl;
    if (i < N) g_cur[i] = excl;
}

// ---------------- CSR scatter: {src byte offset, dinv[src]} ----------------

__global__ void k_scatter(const int* __restrict__ src, const int* __restrict__ dst, int E) {
    int i = blockIdx.x * blockDim.x + threadIdx.x;
    if (i < E) {
        int s = src[i];
        int d = dst[i];
        int p = atomicAdd(&g_cur[d], 1);
        g_cedge[p] = make_int2(s * ROW_BYTES, __float_as_int(g_dinv[s]));
    }
}

// ---------------- propagation: warp-per-node gather ----------------
// hout[n] = dinv_n * ( dinv_n * hin[n] + sum_e dinv_src * hin[src] )
// Edge record fetched warp-uniformly (broadcast); all 32 lanes carry one
// aligned half2 of the 128B row (lanes 25..31 are zero padding).

__global__ void __launch_bounds__(256) k_gather(const __half* __restrict__ hin,
                                                __half* __restrict__ hout, int N) {
    int n = (blockIdx.x * blockDim.x + threadIdx.x) >> 5;
    int lane = threadIdx.x & 31;
    if (n >= N) return;

    int base = g_off[n];
    int end  = g_off[n + 1];
    float dv = g_dinv[n];

    const char* hb = reinterpret_cast<const char*>(hin) + 4 * lane;

    float2 acc;
    {
        float2 f = __half22float2(*reinterpret_cast<const __half2*>(hb + n * ROW_BYTES));
        acc.x = dv * f.x;
        acc.y = dv * f.y;
    }

    #pragma unroll 4
    for (int k = base; k < end; k++) {
        int2 pe = g_cedge[k];                 // warp-uniform broadcast load
        float ww = __int_as_float(pe.y);
        float2 f = __half22float2(*reinterpret_cast<const __half2*>(hb + pe.x));
        acc.x = fmaf(ww, f.x, acc.x);
        acc.y = fmaf(ww, f.y, acc.y);
    }

    acc.x *= dv;
    acc.y *= dv;
    *reinterpret_cast<__half2*>(
        reinterpret_cast<char*>(hout) + n * ROW_BYTES + 4 * lane) =
        __float22half2_rn(acc);
}

// ---------------- projection out = h @ W^T + b ----------------

#define GEMM_NODES 128

__global__ void __launch_bounds__(GEMM_NODES) k_gemm(const __half* __restrict__ h,
                                                     const float* __restrict__ W,
                                                     const float* __restrict__ b,
                                                     float* __restrict__ out, int N) {
    __shared__ float2 Ws2[N_CLS * HCHUNKS];                       // 9400 B
    __shared__ float bs[N_CLS];
    __shared__ __align__(16) char buf[HCHUNKS * GEMM_NODES * 8];  // 25600 B (union)
    float2* ht2 = reinterpret_cast<float2*>(buf);                 // [25][128]
    float*  ot  = reinterpret_cast<float*>(buf);                  // [128*47] (reuse)

    int tid = threadIdx.x;
    for (int i = tid; i < N_CLS * HCHUNKS; i += GEMM_NODES)
        Ws2[i] = reinterpret_cast<const float2*>(W)[i];
    if (tid < N_CLS) bs[tid] = b[tid];

    int n0 = blockIdx.x * GEMM_NODES;
    int nodes = min(GEMM_NODES, N - n0);

    for (int i = tid; i < nodes * HCHUNKS; i += GEMM_NODES) {
        int nl = i / HCHUNKS;
        int c = i - nl * HCHUNKS;
        __half2 v = *reinterpret_cast<const __half2*>(
            reinterpret_cast<const char*>(h) + (size_t)(n0 + nl) * ROW_BYTES + 4 * c);
        ht2[c * GEMM_NODES + nl] = __half22float2(v);
    }
    __syncthreads();

    float2 row[HCHUNKS];
    if (tid < nodes) {
        #pragma unroll
        for (int c = 0; c < HCHUNKS; c++) row[c] = ht2[c * GEMM_NODES + tid];
    }
    __syncthreads();    // ht2 dead; buf becomes ot

    if (tid < nodes) {
        #pragma unroll 1
        for (int cc = 0; cc < N_CLS; cc++) {
            float2 a = make_float2(bs[cc], 0.f);
            const float2* wr = &Ws2[cc * HCHUNKS];
            #pragma unroll
            for (int c = 0; c < HCHUNKS; c++) fma_f32x2(a, row[c], wr[c]);
            ot[tid * N_CLS + cc] = a.x + a.y;
        }
    }
    __syncthreads();

    for (int i = tid; i < nodes * N_CLS; i += GEMM_NODES)
        out[(size_t)n0 * N_CLS + i] = ot[i];
}

// ---------------- launch ----------------

extern "C" void kernel_launch(void* const* d_in, const int* in_sizes, int n_in,
                              void* d_out, int out_size) {
    const float* feat = (const float*)d_in[0];
    const float* W    = (const float*)d_in[1];
    const float* b    = (const float*)d_in[2];
    const int* esrc   = (const int*)d_in[3];
    const int* edst   = (const int*)d_in[4];
    // d_in[5] = K (device scalar); hops statically unrolled to 2.

    int C = in_sizes[2];
    int D = in_sizes[1] / C;
    int N = in_sizes[0] / D;
    int E = in_sizes[3];

    __half* ha; cudaGetSymbolAddress((void**)&ha, g_ha);
    __half* hb; cudaGetSymbolAddress((void**)&hb, g_hb);
    int* cnt;   cudaGetSymbolAddress((void**)&cnt, g_cnt);

    const int T = 256;
    int NB = (N + SCAN_B - 1) / SCAN_B;

    cudaMemsetAsync(cnt, 0, (size_t)N * sizeof(int));
    int conv_work = N * 32;
    int fused_work = (E > conv_work) ? E : conv_work;
    k_count_conv<<<(fused_work + T - 1) / T, T>>>(edst, feat, E, N);
    k_scan1<<<NB, SCAN_B>>>(N);
    k_scan2<<<1, MAX_SB>>>(NB);
    k_scan3<<<(N + 1 + T - 1) / T, T>>>(N, E);
    k_scatter<<<(E + T - 1) / T, T>>>(esrc, edst, E);

    int gblocks = (N * 32 + T - 1) / T;
    k_gather<<<gblocks, T>>>(ha, hb, N);
    k_gather<<<gblocks, T>>>(hb, ha, N);

    k_gemm<<<(N + GEMM_NODES - 1) / GEMM_NODES, GEMM_NODES>>>(ha, W, b, (float*)d_out, N);
}